// round 11
// baseline (speedup 1.0000x reference)
#include <cuda_runtime.h>
#include <cuda_fp16.h>
#include <cstdint>

#define BB 8
#define NN 2048
#define DD 128
#define ALPHA_F 0.2f
#define LOG2E_F 1.4426950408889634f

// ---------------- device scratch (no cudaMalloc allowed) ----------------
__device__ __half   g_Whh[BB * NN * DD];      // 4 MB, [b*N + j][d] fp16
__device__ float    g_es[BB * NN];
__device__ float    g_ed[BB * NN];
__device__ unsigned g_edmax_enc[BB];          // order-preserving encoded fp32 max
__device__ unsigned g_mask[NN * (NN / 32)];   // 512 KB packed adjacency bits

// ---------------- helpers ----------------
__device__ __forceinline__ uint32_t smem_u32(const void* p) {
    uint32_t a;
    asm("{ .reg .u64 t; cvta.to.shared.u64 t, %1; cvt.u32.u64 %0, t; }" : "=r"(a) : "l"(p));
    return a;
}
__device__ __forceinline__ unsigned fenc(float x) {
    unsigned u = __float_as_uint(x);
    return (u & 0x80000000u) ? ~u : (u | 0x80000000u);
}
__device__ __forceinline__ float fdec(unsigned e) {
    return (e & 0x80000000u) ? __uint_as_float(e ^ 0x80000000u) : __uint_as_float(~e);
}
__device__ __forceinline__ uint32_t ex2h2(float a, float b) {
    __half2 h = __floats2half2_rn(a, b);
    uint32_t in = *(uint32_t*)&h, r;
    asm("ex2.approx.f16x2 %0, %1;" : "=r"(r) : "r"(in));
    return r;
}
__device__ __forceinline__ void cpasync16(uint32_t dst, const void* src) {
    asm volatile("cp.async.ca.shared.global [%0], [%1], 16;" :: "r"(dst), "l"(src));
}
#define CP_COMMIT() asm volatile("cp.async.commit_group;" ::: "memory")
#define CP_WAIT1()  asm volatile("cp.async.wait_group 1;" ::: "memory")

__device__ __forceinline__ void ldm4(uint32_t* r, uint32_t a) {
    asm volatile("ldmatrix.sync.aligned.m8n8.x4.shared.b16 {%0,%1,%2,%3}, [%4];"
                 : "=r"(r[0]), "=r"(r[1]), "=r"(r[2]), "=r"(r[3]) : "r"(a));
}
__device__ __forceinline__ void ldm4t(uint32_t* r, uint32_t a) {
    asm volatile("ldmatrix.sync.aligned.m8n8.x4.trans.shared.b16 {%0,%1,%2,%3}, [%4];"
                 : "=r"(r[0]), "=r"(r[1]), "=r"(r[2]), "=r"(r[3]) : "r"(a));
}
__device__ __forceinline__ void mma16(float* d, const uint32_t* a, const uint32_t* b) {
    asm volatile(
        "mma.sync.aligned.m16n8k16.row.col.f32.f16.f16.f32 "
        "{%0,%1,%2,%3}, {%4,%5,%6,%7}, {%8,%9}, {%0,%1,%2,%3};"
        : "+f"(d[0]), "+f"(d[1]), "+f"(d[2]), "+f"(d[3])
        : "r"(a[0]), "r"(a[1]), "r"(a[2]), "r"(a[3]), "r"(b[0]), "r"(b[1]));
}

// ===========================================================================
// Kernel 0: pack adjacency bitmask (blocks 0..511) + init edmax (block 512)
// ===========================================================================
__global__ __launch_bounds__(256) void k_pre(const int* __restrict__ adj) {
    if (blockIdx.x >= 512) {
        if (threadIdx.x < BB) g_edmax_enc[threadIdx.x] = 0u;  // encodes -max float
        return;
    }
    const int g = blockIdx.x * 256 + threadIdx.x;
    const int i = g >> 6, w = g & 63;
    const int4* a4 = ((const int4*)adj) + (size_t)i * 512 + w * 8;
    unsigned bits = 0;
#pragma unroll
    for (int q = 0; q < 8; q++) {
        int4 v = __ldg(&a4[q]);
        bits |= (v.x > 0 ? 1u : 0u) << (q * 4 + 0);
        bits |= (v.y > 0 ? 1u : 0u) << (q * 4 + 1);
        bits |= (v.z > 0 ? 1u : 0u) << (q * 4 + 2);
        bits |= (v.w > 0 ? 1u : 0u) << (q * 4 + 3);
    }
    g_mask[g] = bits;
}

// ===========================================================================
// Kernel 1: tensor-core Wh = h@W (fp16 mma), exact fp32 e_src/e_dst via
// precomputed wsrc = W@a_src, wdst = W@a_dst; block edmax via atomicMax.
// 128 blocks x 256 threads (8 warps, 4M x 2N), 128 rows per block.
// smem: sW[128][136]h @0 (34816) | hA[128][136]h @34816 | wvec[256]f @69632
//       redmax[8]f @70656 ; total 70688
// ===========================================================================
#define PJ_SW   0u
#define PJ_HA   34816u
#define PJ_WV   69632u
#define PJ_RM   70656u
#define PJ_SMEM 70688u
#define PJ_PIT  272u

__global__ __launch_bounds__(256) void k_proj(const float* __restrict__ h,
                                              const float* __restrict__ W,
                                              const float* __restrict__ a_src,
                                              const float* __restrict__ a_dst) {
    extern __shared__ __align__(16) char smem[];
    const uint32_t sbase = smem_u32(smem);

    const int t = threadIdx.x, wid = t >> 5, lane = t & 31;
    const int gid = lane >> 2, tid4 = lane & 3;
    const int wm = wid & 3, wn = wid >> 2;
    const int grow0 = blockIdx.x * 128;          // global row (b*N + n)
    const int b = blockIdx.x >> 4;

    // ---- phase A: stage W -> sW (fp16) ----
    const float4* W4 = (const float4*)W;
#pragma unroll
    for (int q = 0; q < 16; q++) {
        int idx = t + 256 * q;
        int rr = idx >> 5, cc = idx & 31;
        float4 v = __ldg(&W4[idx]);
        __half2 p01 = __floats2half2_rn(v.x, v.y), p23 = __floats2half2_rn(v.z, v.w);
        uint2 pk; pk.x = *(uint32_t*)&p01; pk.y = *(uint32_t*)&p23;
        *(uint2*)(smem + PJ_SW + (uint32_t)(rr * PJ_PIT + cc * 8)) = pk;
    }

    // ---- phase B: wvec = W @ a (fp32, W rows L2-hot after phase A) ----
    {
        const int d = t & 127;
        const float* av = (t < 128) ? a_src : a_dst;
        const float* wr = W + d * 128;
        float s = 0.f;
#pragma unroll 8
        for (int e = 0; e < 128; e++) s += __ldg(wr + e) * __ldg(av + e);
        *(float*)(smem + PJ_WV + ((t < 128) ? d : 128 + d) * 4) = s;
    }
    __syncthreads();  // wvec ready (sW also done)

    // ---- phase C: stage h -> hA (fp16) + es/ed fp32 dots ----
    {
        const int row = t >> 1, hf = t & 1;
        const float4* hr = ((const float4*)(h + (size_t)(grow0 + row) * 128)) + hf * 16;
        const float* ws = (const float*)(smem + PJ_WV) + hf * 64;
        const float* wd = ws + 128;
        float es = 0.f, ed = 0.f;
#pragma unroll
        for (int q = 0; q < 16; q++) {
            float4 v = __ldg(&hr[q]);
            es += v.x * ws[q * 4] + v.y * ws[q * 4 + 1] + v.z * ws[q * 4 + 2] + v.w * ws[q * 4 + 3];
            ed += v.x * wd[q * 4] + v.y * wd[q * 4 + 1] + v.z * wd[q * 4 + 2] + v.w * wd[q * 4 + 3];
            __half2 p01 = __floats2half2_rn(v.x, v.y), p23 = __floats2half2_rn(v.z, v.w);
            uint2 pk; pk.x = *(uint32_t*)&p01; pk.y = *(uint32_t*)&p23;
            *(uint2*)(smem + PJ_HA + (uint32_t)(row * PJ_PIT + (hf * 16 + q) * 8)) = pk;
        }
        es += __shfl_xor_sync(0xffffffffu, es, 1);
        ed += __shfl_xor_sync(0xffffffffu, ed, 1);
        if (hf == 0) {
            g_es[grow0 + row] = es;
            g_ed[grow0 + row] = ed;
        }
        // warp -> block max of ed
        float m = ed;
#pragma unroll
        for (int o = 16; o > 1; o >>= 1) m = fmaxf(m, __shfl_xor_sync(0xffffffffu, m, o));
        if (lane == 0) *(float*)(smem + PJ_RM + wid * 4) = m;
    }
    __syncthreads();  // hA + redmax ready
    if (t == 0) {
        float m = *(float*)(smem + PJ_RM);
#pragma unroll
        for (int q = 1; q < 8; q++) m = fmaxf(m, *(float*)(smem + PJ_RM + q * 4));
        atomicMax(&g_edmax_enc[b], fenc(m));
    }

    // ---- phase D: MMA hA @ sW -> Whh ----
    const uint32_t offA = (uint32_t)((wm * 32 + (lane & 15)) * PJ_PIT + (lane >> 4) * 16);
    const uint32_t offB = (uint32_t)((((lane >> 3) & 1) * 8 + (lane & 7)) * PJ_PIT +
                                     wn * 128 + (lane >> 4) * 16);
    float acc[2][8][4];
#pragma unroll
    for (int mt = 0; mt < 2; mt++)
#pragma unroll
        for (int nt = 0; nt < 8; nt++)
#pragma unroll
            for (int c = 0; c < 4; c++) acc[mt][nt][c] = 0.f;

#pragma unroll
    for (int kb = 0; kb < 8; kb++) {
        uint32_t A0[4], A1[4], Bv[4][4];
        ldm4(A0, sbase + PJ_HA + offA + kb * 32);
        ldm4(A1, sbase + PJ_HA + offA + 16 * PJ_PIT + kb * 32);
#pragma unroll
        for (int nb2 = 0; nb2 < 4; nb2++)
            ldm4t(Bv[nb2], sbase + PJ_SW + offB + nb2 * 32 + kb * 16 * PJ_PIT);
#pragma unroll
        for (int nb2 = 0; nb2 < 4; nb2++) {
            mma16(acc[0][nb2 * 2],     A0, &Bv[nb2][0]);
            mma16(acc[0][nb2 * 2 + 1], A0, &Bv[nb2][2]);
            mma16(acc[1][nb2 * 2],     A1, &Bv[nb2][0]);
            mma16(acc[1][nb2 * 2 + 1], A1, &Bv[nb2][2]);
        }
    }

    // epilogue: fp32 acc -> fp16 Whh
    uint32_t* Whu = (uint32_t*)g_Whh;
#pragma unroll
    for (int mt = 0; mt < 2; mt++) {
        int rA = grow0 + wm * 32 + mt * 16 + gid;
        int rB = rA + 8;
#pragma unroll
        for (int nt = 0; nt < 8; nt++) {
            int col = wn * 64 + nt * 8 + tid4 * 2;
            __half2 va = __floats2half2_rn(acc[mt][nt][0], acc[mt][nt][1]);
            __half2 vb = __floats2half2_rn(acc[mt][nt][2], acc[mt][nt][3]);
            Whu[((size_t)rA * 128 + col) >> 1] = *(uint32_t*)&va;
            Whu[((size_t)rB * 128 + col) >> 1] = *(uint32_t*)&vb;
        }
    }
}

// ===========================================================================
// Kernel 2: fused masked attention + f16x2 exp + fp16 mma.sync P@Wh
// grid (32, 8): 64 i-rows per block, 256 threads (8 warps, 4M x 2N), 3 CTAs/SM.
// Row sums via MMA against all-ones B tile.
// ===========================================================================
#define WHS_OFF  0u
#define WHS_BUF  8704u
#define WHS_PIT  272u
#define PS_OFF   26112u
#define PS_BUF   5120u
#define PS_PIT   80u
#define EDS_OFF  36352u
#define SMEM_SZ  44544u
#define ONES_H2  0x3C003C00u

__global__ __launch_bounds__(256, 3) void k_attn(float* __restrict__ out) {
    extern __shared__ __align__(16) char smem[];
    const uint32_t sbase = smem_u32(smem);

    const int t = threadIdx.x, wid = t >> 5, lane = t & 31;
    const int gid = lane >> 2, tid4 = lane & 3;
    const int wm = wid & 3, wn = wid >> 2;
    const int b = blockIdx.y, i0 = blockIdx.x * 64;
    const int row = t >> 2, q4 = t & 3;

    const __half* Whb = g_Whh + (size_t)b * NN * DD;

    const uint32_t offA = (uint32_t)((wm * 16 + (lane & 15)) * PS_PIT + (lane >> 4) * 16);
    const uint32_t offB = (uint32_t)((((lane >> 3) & 1) * 8 + (lane & 7)) * WHS_PIT +
                                     wn * 128 + (lane >> 4) * 16);

    // ---- prologue: cp Wh tiles 0,1; load eds ----
#pragma unroll
    for (int q = 0; q < 2; q++) {
        int idx = t + 256 * q;
        int rr = idx >> 4, cc = idx & 15;
        cpasync16(sbase + WHS_OFF + (uint32_t)(rr * WHS_PIT + cc * 16),
                  Whb + (size_t)rr * DD + cc * 8);
    }
    CP_COMMIT();
#pragma unroll
    for (int q = 0; q < 2; q++) {
        int idx = t + 256 * q;
        int rr = idx >> 4, cc = idx & 15;
        cpasync16(sbase + WHS_OFF + WHS_BUF + (uint32_t)(rr * WHS_PIT + cc * 16),
                  Whb + (size_t)(32 + rr) * DD + cc * 8);
    }
    CP_COMMIT();
    {
        float4* ed4 = (float4*)(smem + EDS_OFF);
        const float4* edsrc = ((const float4*)g_ed) + b * 512;
        ed4[t] = edsrc[t];
        ed4[t + 256] = edsrc[t + 256];
    }
    __syncthreads();

    const float esr = __ldg(g_es + b * NN + i0 + row);
    const float edm = fdec(g_edmax_enc[b]);
    const float xm = esr + edm;
    const float m2r = fmaxf(xm, ALPHA_F * xm) * LOG2E_F;

    const uint8_t* mrow = ((const uint8_t*)g_mask) + (size_t)(i0 + row) * 256 + q4;

    float acc[8][4];
#pragma unroll
    for (int nt = 0; nt < 8; nt++)
#pragma unroll
        for (int c = 0; c < 4; c++) acc[nt][c] = 0.f;
    float accl[4] = {0.f, 0.f, 0.f, 0.f};
    const uint32_t bones[2] = {ONES_H2, ONES_H2};

    // ---- produce P(0) ----
    {
        unsigned mb = (unsigned)__ldg(mrow);
        const float* edt = (const float*)(smem + EDS_OFF) + q4 * 8;
        float4 e0 = *(const float4*)edt, e1 = *(const float4*)(edt + 4);
        float a0, a1, a2, a3, a4, a5, a6, a7;
        {
            float x, l;
            x = esr + e0.x; l = fmaxf(x, ALPHA_F * x); a0 = (mb & 1)   ? fmaf(l, LOG2E_F, -m2r) : -1e4f;
            x = esr + e0.y; l = fmaxf(x, ALPHA_F * x); a1 = (mb & 2)   ? fmaf(l, LOG2E_F, -m2r) : -1e4f;
            x = esr + e0.z; l = fmaxf(x, ALPHA_F * x); a2 = (mb & 4)   ? fmaf(l, LOG2E_F, -m2r) : -1e4f;
            x = esr + e0.w; l = fmaxf(x, ALPHA_F * x); a3 = (mb & 8)   ? fmaf(l, LOG2E_F, -m2r) : -1e4f;
            x = esr + e1.x; l = fmaxf(x, ALPHA_F * x); a4 = (mb & 16)  ? fmaf(l, LOG2E_F, -m2r) : -1e4f;
            x = esr + e1.y; l = fmaxf(x, ALPHA_F * x); a5 = (mb & 32)  ? fmaf(l, LOG2E_F, -m2r) : -1e4f;
            x = esr + e1.z; l = fmaxf(x, ALPHA_F * x); a6 = (mb & 64)  ? fmaf(l, LOG2E_F, -m2r) : -1e4f;
            x = esr + e1.w; l = fmaxf(x, ALPHA_F * x); a7 = (mb & 128) ? fmaf(l, LOG2E_F, -m2r) : -1e4f;
        }
        uint4 pv = make_uint4(ex2h2(a0, a1), ex2h2(a2, a3), ex2h2(a4, a5), ex2h2(a6, a7));
        *(uint4*)(smem + PS_OFF + (uint32_t)(row * PS_PIT + q4 * 16)) = pv;
    }
    CP_WAIT1();
    __syncthreads();

    int wbuf = 2, rbuf = 0;
    for (int k = 0; k < 64; k++) {
        // ---- stage 1: cp.async Wh(k+2) ----
        if (k < 62) {
            const int j2 = (k + 2) * 32;
            uint32_t dstb = sbase + WHS_OFF + (uint32_t)wbuf * WHS_BUF;
#pragma unroll
            for (int q = 0; q < 2; q++) {
                int idx = t + 256 * q;
                int rr = idx >> 4, cc = idx & 15;
                cpasync16(dstb + (uint32_t)(rr * WHS_PIT + cc * 16),
                          Whb + (size_t)(j2 + rr) * DD + cc * 8);
            }
        }
        CP_COMMIT();

        // ---- stage 2: produce P(k+1) ----
        if (k < 63) {
            const int kt = k + 1;
            unsigned mb = (unsigned)__ldg(mrow + kt * 4);
            const float* edt = (const float*)(smem + EDS_OFF) + kt * 32 + q4 * 8;
            float4 e0 = *(const float4*)edt, e1 = *(const float4*)(edt + 4);
            float a0, a1, a2, a3, a4, a5, a6, a7;
            {
                float x, l;
                x = esr + e0.x; l = fmaxf(x, ALPHA_F * x); a0 = (mb & 1)   ? fmaf(l, LOG2E_F, -m2r) : -1e4f;
                x = esr + e0.y; l = fmaxf(x, ALPHA_F * x); a1 = (mb & 2)   ? fmaf(l, LOG2E_F, -m2r) : -1e4f;
                x = esr + e0.z; l = fmaxf(x, ALPHA_F * x); a2 = (mb & 4)   ? fmaf(l, LOG2E_F, -m2r) : -1e4f;
                x = esr + e0.w; l = fmaxf(x, ALPHA_F * x); a3 = (mb & 8)   ? fmaf(l, LOG2E_F, -m2r) : -1e4f;
                x = esr + e1.x; l = fmaxf(x, ALPHA_F * x); a4 = (mb & 16)  ? fmaf(l, LOG2E_F, -m2r) : -1e4f;
                x = esr + e1.y; l = fmaxf(x, ALPHA_F * x); a5 = (mb & 32)  ? fmaf(l, LOG2E_F, -m2r) : -1e4f;
                x = esr + e1.z; l = fmaxf(x, ALPHA_F * x); a6 = (mb & 64)  ? fmaf(l, LOG2E_F, -m2r) : -1e4f;
                x = esr + e1.w; l = fmaxf(x, ALPHA_F * x); a7 = (mb & 128) ? fmaf(l, LOG2E_F, -m2r) : -1e4f;
            }
            uint4 pv = make_uint4(ex2h2(a0, a1), ex2h2(a2, a3), ex2h2(a4, a5), ex2h2(a6, a7));
            *(uint4*)(smem + PS_OFF + (uint32_t)((kt & 1) * PS_BUF) +
                      (uint32_t)(row * PS_PIT + q4 * 16)) = pv;
        }

        // ---- stage 3: MMA(k) ----
        {
            const uint32_t psB = sbase + PS_OFF + (uint32_t)((k & 1) * PS_BUF);
            const uint32_t whB = sbase + WHS_OFF + (uint32_t)rbuf * WHS_BUF;
#pragma unroll
            for (int kb = 0; kb < 2; kb++) {
                uint32_t A[4], Bv[4][4];
                ldm4(A, psB + offA + kb * 32);
#pragma unroll
                for (int nb2 = 0; nb2 < 4; nb2++)
                    ldm4t(Bv[nb2], whB + offB + nb2 * 32 + kb * 16 * WHS_PIT);
#pragma unroll
                for (int nb2 = 0; nb2 < 4; nb2++) {
                    mma16(acc[nb2 * 2],     A, &Bv[nb2][0]);
                    mma16(acc[nb2 * 2 + 1], A, &Bv[nb2][2]);
                }
                mma16(accl, A, bones);  // row sums
            }
        }

        CP_WAIT1();
        __syncthreads();

        wbuf = wbuf == 2 ? 0 : wbuf + 1;
        rbuf = rbuf == 2 ? 0 : rbuf + 1;
    }

    // ---- epilogue: normalize by MMA-computed row sums, write ----
    const float ivA = 1.0f / accl[0];
    const float ivB = 1.0f / accl[2];
    float2* out2 = (float2*)out;
    {
        int rA = wm * 16 + gid;
        int rB = rA + 8;
        size_t baseA = ((size_t)(b * NN + i0 + rA) * 128) >> 1;
        size_t baseB = ((size_t)(b * NN + i0 + rB) * 128) >> 1;
#pragma unroll
        for (int nt = 0; nt < 8; nt++) {
            int colh = (wn * 64 + nt * 8 + tid4 * 2) >> 1;
            out2[baseA + colh] = make_float2(acc[nt][0] * ivA, acc[nt][1] * ivA);
            out2[baseB + colh] = make_float2(acc[nt][2] * ivB, acc[nt][3] * ivB);
        }
    }
}

// ===========================================================================
extern "C" void kernel_launch(void* const* d_in, const int* in_sizes, int n_in,
                              void* d_out, int out_size) {
    const float* h     = (const float*)d_in[0];
    const int*   adj   = (const int*)d_in[1];
    const float* W     = (const float*)d_in[2];
    const float* a_src = (const float*)d_in[3];
    const float* a_dst = (const float*)d_in[4];
    float* out = (float*)d_out;

    cudaFuncSetAttribute(k_proj, cudaFuncAttributeMaxDynamicSharedMemorySize, PJ_SMEM);
    cudaFuncSetAttribute(k_attn, cudaFuncAttributeMaxDynamicSharedMemorySize, SMEM_SZ);

    k_pre<<<513, 256>>>(adj);
    k_proj<<<128, 256, PJ_SMEM>>>(h, W, a_src, a_dst);
    k_attn<<<dim3(32, 8), 256, SMEM_SZ>>>(out);
}